// round 2
// baseline (speedup 1.0000x reference)
#include <cuda_runtime.h>
#include <cstdint>

#define HID 128
#define MAXN 50000

// ---------------- scratch (device globals; no allocation allowed) ----------------
__device__ __align__(256) float g_z[MAXN * HID];     // raw (pre-BN) layer output
__device__ __align__(256) float g_agg[MAXN * HID];   // edge aggregation
__device__ __align__(256) float g_t[MAXN * HID];     // post-GEMM1 pre-BN
__device__ __align__(256) float g_stat[2 * HID];     // [sum | sumsq]
__device__ __align__(256) float g_sc_in[HID];        // BN scale applied to z on load
__device__ __align__(256) float g_sh_in[HID];        // BN shift applied to z on load
__device__ __align__(256) float g_sc_t[HID];         // BN scale for t
__device__ __align__(256) float g_sh_t[HID];         // BN shift for t

// ---------------- f32x2 helpers (sm_100+ packed fp32 pipe) ----------------
__device__ __forceinline__ unsigned long long pk2(float a) {
    unsigned long long r;
    asm("mov.b64 %0, {%1, %1};" : "=l"(r) : "f"(a));
    return r;
}
__device__ __forceinline__ void fma2(unsigned long long& d, unsigned long long a, unsigned long long b) {
    asm("fma.rn.f32x2 %0, %1, %2, %0;" : "+l"(d) : "l"(a), "l"(b));
}
__device__ __forceinline__ float2 upk(unsigned long long v) {
    float2 r;
    asm("mov.b64 {%0, %1}, %2;" : "=f"(r.x), "=f"(r.y) : "l"(v));
    return r;
}

// ---------------- init: identity BN for layer 0 input ----------------
__global__ void init_scale_kernel() {
    int c = threadIdx.x;
    g_sc_in[c] = 1.0f;
    g_sh_in[c] = 0.0f;
}

// ---------------- edge kernel: warp per edge, v4 reduction atomics ----------------
__global__ void edge_kernel(const float* __restrict__ z, const float* __restrict__ ea,
                            const int* __restrict__ srcI, const int* __restrict__ dstI,
                            int E) {
    int t = blockIdx.x * blockDim.x + threadIdx.x;
    int e = t >> 5;
    if (e >= E) return;
    int lane = t & 31;
    int src = __ldg(srcI + e);
    int dst = __ldg(dstI + e);
    float4 sc = __ldg((const float4*)g_sc_in + lane);
    float4 sh = __ldg((const float4*)g_sh_in + lane);
    float4 zv = __ldg((const float4*)(z + (size_t)src * HID) + lane);
    float4 ev = __ldcs((const float4*)(ea + (size_t)e * HID) + lane);  // streaming: read-once
    float4 m;
    m.x = fmaxf(fmaf(sc.x, zv.x, sh.x) + ev.x, 0.0f);
    m.y = fmaxf(fmaf(sc.y, zv.y, sh.y) + ev.y, 0.0f);
    m.z = fmaxf(fmaf(sc.z, zv.z, sh.z) + ev.z, 0.0f);
    m.w = fmaxf(fmaf(sc.w, zv.w, sh.w) + ev.w, 0.0f);
    float* p = g_agg + (size_t)dst * HID + lane * 4;
    asm volatile("red.global.add.v4.f32 [%0], {%1,%2,%3,%4};"
                 :: "l"(p), "f"(m.x), "f"(m.y), "f"(m.z), "f"(m.w) : "memory");
}

// ---------------- fused GEMM (+ optional input BN/ReLU, residual add, output ReLU, BN stats) ----
// C[M,128] = pre(A) @ W + bias ; thread tile 4 rows x 8 cols, BM=64, 256 threads
static const int GEMM_SMEM = (HID * HID + 64 * 132) * 4;  // 99328 bytes

template <bool HAS_A2, bool RELU_IN, bool RELU_OUT, bool STATS>
__global__ void __launch_bounds__(256) gemm_kernel(
    const float* __restrict__ A, const float* __restrict__ A2,
    const float* __restrict__ sc, const float* __restrict__ sh,
    const float* __restrict__ W, const float* __restrict__ bias,
    float* __restrict__ out, int M) {
    extern __shared__ float smem[];
    float* Ws = smem;              // [128][128]
    float* As = smem + HID * HID;  // [64][132] padded (bank-conflict-free)

    const int tid = threadIdx.x;
    const int tx = tid & 15;   // col group: cols tx*8 .. tx*8+7
    const int ty = tid >> 4;   // row group: rows ty*4 .. ty*4+3
    const int row0 = blockIdx.x * 64;

    // stage W (16384 floats = 4096 float4)
    const float4* Wg = (const float4*)W;
    float4* Ws4 = (float4*)Ws;
#pragma unroll
    for (int i = 0; i < 16; i++) Ws4[tid + 256 * i] = __ldg(Wg + tid + 256 * i);

    // stage A tile with input transform
    for (int i = tid; i < 64 * 32; i += 256) {
        int r = i >> 5, c4 = i & 31;
        int gr = row0 + r;
        float4 v = make_float4(0.f, 0.f, 0.f, 0.f);
        if (gr < M) {
            float4 zv = __ldg((const float4*)(A + (size_t)gr * HID) + c4);
            float4 s4 = __ldg((const float4*)sc + c4);
            float4 h4 = __ldg((const float4*)sh + c4);
            v.x = fmaf(s4.x, zv.x, h4.x);
            v.y = fmaf(s4.y, zv.y, h4.y);
            v.z = fmaf(s4.z, zv.z, h4.z);
            v.w = fmaf(s4.w, zv.w, h4.w);
            if (RELU_IN) {
                v.x = fmaxf(v.x, 0.f); v.y = fmaxf(v.y, 0.f);
                v.z = fmaxf(v.z, 0.f); v.w = fmaxf(v.w, 0.f);
            }
            if (HAS_A2) {
                float4 g4 = __ldg((const float4*)(A2 + (size_t)gr * HID) + c4);
                v.x += g4.x; v.y += g4.y; v.z += g4.z; v.w += g4.w;
            }
        }
        *(float4*)&As[r * 132 + c4 * 4] = v;
    }
    __syncthreads();

    unsigned long long acc[16];
#pragma unroll
    for (int i = 0; i < 16; i++) acc[i] = 0ull;

    const int arow = ty * 4;
#pragma unroll 2
    for (int kk = 0; kk < HID; kk += 4) {
        float ar[4][4];
#pragma unroll
        for (int r = 0; r < 4; r++)
            *(float4*)ar[r] = *(const float4*)&As[(arow + r) * 132 + kk];
#pragma unroll
        for (int j = 0; j < 4; j++) {
            ulonglong2 wA = *(const ulonglong2*)&Ws[(kk + j) * HID + tx * 8];
            ulonglong2 wB = *(const ulonglong2*)&Ws[(kk + j) * HID + tx * 8 + 4];
#pragma unroll
            for (int r = 0; r < 4; r++) {
                unsigned long long pa = pk2(ar[r][j]);
                fma2(acc[r * 4 + 0], pa, wA.x);
                fma2(acc[r * 4 + 1], pa, wA.y);
                fma2(acc[r * 4 + 2], pa, wB.x);
                fma2(acc[r * 4 + 3], pa, wB.y);
            }
        }
    }

    // epilogue
    float bb[8];
    *(float4*)&bb[0] = __ldg((const float4*)bias + tx * 2);
    *(float4*)&bb[4] = __ldg((const float4*)bias + tx * 2 + 1);
    float csum[8], csq[8];
#pragma unroll
    for (int j = 0; j < 8; j++) { csum[j] = 0.f; csq[j] = 0.f; }

#pragma unroll
    for (int r = 0; r < 4; r++) {
        int gr = row0 + arow + r;
        if (gr < M) {
            float v[8];
#pragma unroll
            for (int p = 0; p < 4; p++) {
                float2 u = upk(acc[r * 4 + p]);
                v[2 * p] = u.x + bb[2 * p];
                v[2 * p + 1] = u.y + bb[2 * p + 1];
            }
            if (RELU_OUT) {
#pragma unroll
                for (int j = 0; j < 8; j++) v[j] = fmaxf(v[j], 0.f);
            }
            float4 s0 = make_float4(v[0], v[1], v[2], v[3]);
            float4 s1 = make_float4(v[4], v[5], v[6], v[7]);
            *(float4*)(out + (size_t)gr * HID + tx * 8) = s0;
            *(float4*)(out + (size_t)gr * HID + tx * 8 + 4) = s1;
            if (STATS) {
#pragma unroll
                for (int j = 0; j < 8; j++) { csum[j] += v[j]; csq[j] += v[j] * v[j]; }
            }
        }
    }

    if (STATS) {
        float* red = As;  // reuse (2048 floats needed of 8448)
        __syncthreads();
#pragma unroll
        for (int j = 0; j < 8; j++) red[ty * HID + tx * 8 + j] = csum[j];
        __syncthreads();
        for (int s = 8; s > 0; s >>= 1) {
            if (ty < s) {
#pragma unroll
                for (int j = 0; j < 8; j++)
                    red[ty * HID + tx * 8 + j] += red[(ty + s) * HID + tx * 8 + j];
            }
            __syncthreads();
        }
        if (ty == 0) {
#pragma unroll
            for (int j = 0; j < 8; j++) atomicAdd(&g_stat[tx * 8 + j], red[tx * 8 + j]);
        }
        __syncthreads();
#pragma unroll
        for (int j = 0; j < 8; j++) red[ty * HID + tx * 8 + j] = csq[j];
        __syncthreads();
        for (int s = 8; s > 0; s >>= 1) {
            if (ty < s) {
#pragma unroll
                for (int j = 0; j < 8; j++)
                    red[ty * HID + tx * 8 + j] += red[(ty + s) * HID + tx * 8 + j];
            }
            __syncthreads();
        }
        if (ty == 0) {
#pragma unroll
            for (int j = 0; j < 8; j++) atomicAdd(&g_stat[HID + tx * 8 + j], red[tx * 8 + j]);
        }
    }
}

// ---------------- finalize BN: scale = g*rsqrt(var+eps), shift = b - scale*mu ----------------
__global__ void finalize_kernel(const float* __restrict__ gamma, const float* __restrict__ beta,
                                float* __restrict__ sco, float* __restrict__ sho, float invN) {
    int c = threadIdx.x;
    float mu = g_stat[c] * invN;
    float var = g_stat[HID + c] * invN - mu * mu;
    float s = gamma[c] * rsqrtf(var + 1e-5f);
    sco[c] = s;
    sho[c] = beta[c] - s * mu;
}

// ---------------- launcher ----------------
extern "C" void kernel_launch(void* const* d_in, const int* in_sizes, int n_in,
                              void* d_out, int out_size) {
    const float* x = (const float*)d_in[0];
    const int* ei = (const int*)d_in[1];        // int32: JAX x64 is disabled by default
    const float* ea = (const float*)d_in[2];
    const float* W1 = (const float*)d_in[3];
    const float* b1 = (const float*)d_in[4];
    const float* g1 = (const float*)d_in[5];
    const float* be1 = (const float*)d_in[6];
    const float* W2 = (const float*)d_in[7];
    const float* b2 = (const float*)d_in[8];
    const float* bn_g = (const float*)d_in[9];
    const float* bn_b = (const float*)d_in[10];

    int M = in_sizes[0] / HID;
    int E = in_sizes[2] / HID;
    float* out = (float*)d_out;

    void *agg_p, *stat_p, *z_p, *t_p, *scin_p, *shin_p, *sct_p, *sht_p;
    cudaGetSymbolAddress(&agg_p, g_agg);
    cudaGetSymbolAddress(&stat_p, g_stat);
    cudaGetSymbolAddress(&z_p, g_z);
    cudaGetSymbolAddress(&t_p, g_t);
    cudaGetSymbolAddress(&scin_p, g_sc_in);
    cudaGetSymbolAddress(&shin_p, g_sh_in);
    cudaGetSymbolAddress(&sct_p, g_sc_t);
    cudaGetSymbolAddress(&sht_p, g_sh_t);

    cudaFuncSetAttribute(gemm_kernel<true, false, false, true>,
                         cudaFuncAttributeMaxDynamicSharedMemorySize, GEMM_SMEM);
    cudaFuncSetAttribute(gemm_kernel<false, true, true, true>,
                         cudaFuncAttributeMaxDynamicSharedMemorySize, GEMM_SMEM);
    cudaFuncSetAttribute(gemm_kernel<false, true, true, false>,
                         cudaFuncAttributeMaxDynamicSharedMemorySize, GEMM_SMEM);

    const float* zscale = (const float*)scin_p;
    const float* zshift = (const float*)shin_p;
    const float* tscale = (const float*)sct_p;
    const float* tshift = (const float*)sht_p;

    init_scale_kernel<<<1, HID>>>();

    int eb = (int)(((long long)E * 32 + 255) / 256);
    int gb = (M + 63) / 64;
    float invN = 1.0f / (float)M;

    for (int i = 0; i < 4; i++) {
        const float* zsrc = (i == 0) ? x : (const float*)z_p;
        cudaMemsetAsync(agg_p, 0, (size_t)M * HID * sizeof(float));
        cudaMemsetAsync(stat_p, 0, 2 * HID * sizeof(float));

        edge_kernel<<<eb, 256>>>(zsrc, ea, ei, ei + E, E);

        gemm_kernel<true, false, false, true><<<gb, 256, GEMM_SMEM>>>(
            zsrc, (const float*)agg_p, zscale, zshift,
            W1 + (size_t)i * HID * HID, b1 + (size_t)i * HID, (float*)t_p, M);

        finalize_kernel<<<1, HID>>>(g1 + (size_t)i * HID, be1 + (size_t)i * HID,
                                    (float*)sct_p, (float*)sht_p, invN);

        cudaMemsetAsync(stat_p, 0, 2 * HID * sizeof(float));

        if (i < 3) {
            gemm_kernel<false, true, true, true><<<gb, 256, GEMM_SMEM>>>(
                (const float*)t_p, nullptr, tscale, tshift,
                W2 + (size_t)i * HID * HID, b2 + (size_t)i * HID, (float*)z_p, M);
            finalize_kernel<<<1, HID>>>(bn_g + (size_t)i * HID, bn_b + (size_t)i * HID,
                                        (float*)scin_p, (float*)shin_p, invN);
        } else {
            gemm_kernel<false, true, true, false><<<gb, 256, GEMM_SMEM>>>(
                (const float*)t_p, nullptr, tscale, tshift,
                W2 + (size_t)i * HID * HID, b2 + (size_t)i * HID, out, M);
        }
    }
}

// round 3
// speedup vs baseline: 1.0482x; 1.0482x over previous
#include <cuda_runtime.h>
#include <cstdint>

#define HID 128
#define MAXN 50000
#define MAXE 640000

// ---------------- scratch (device globals; no allocation allowed) ----------------
__device__ __align__(256) float g_z[MAXN * HID];     // raw (pre-BN) layer output
__device__ __align__(256) float g_agg[MAXN * HID];   // edge aggregation
__device__ __align__(256) float g_t[MAXN * HID];     // post-GEMM1 pre-BN
__device__ __align__(256) float g_stat_t[2 * HID];   // stats of t (after GEMM1)
__device__ __align__(256) float g_stat_z[2 * HID];   // stats of z (after GEMM2)
__device__ int g_cnt[MAXN];                          // histogram / scatter cursor
__device__ int g_rowptr[MAXN + 1];
__device__ int g_elist[MAXE];

// ---------------- f32x2 helpers (sm_100+ packed fp32 pipe) ----------------
__device__ __forceinline__ unsigned long long pk2(float a) {
    unsigned long long r;
    asm("mov.b64 %0, {%1, %1};" : "=l"(r) : "f"(a));
    return r;
}
__device__ __forceinline__ void fma2(unsigned long long& d, unsigned long long a, unsigned long long b) {
    asm("fma.rn.f32x2 %0, %1, %2, %0;" : "+l"(d) : "l"(a), "l"(b));
}
__device__ __forceinline__ float2 upk(unsigned long long v) {
    float2 r;
    asm("mov.b64 {%0, %1}, %2;" : "=f"(r.x), "=f"(r.y) : "l"(v));
    return r;
}

// ================= CSR build =================
__global__ void hist_kernel(const int* __restrict__ dst, int E) {
    int i = blockIdx.x * blockDim.x + threadIdx.x;
    if (i < E) atomicAdd(&g_cnt[dst[i]], 1);
}

__global__ void __launch_bounds__(1024) scan_kernel(int N, int E) {
    __shared__ int part[1024];
    int tid = threadIdx.x;
    int chunk = (N + 1023) / 1024;
    int base = tid * chunk;
    int s = 0;
    for (int j = 0; j < chunk; j++) {
        int idx = base + j;
        if (idx < N) s += g_cnt[idx];
    }
    part[tid] = s;
    __syncthreads();
    for (int off = 1; off < 1024; off <<= 1) {
        int v = (tid >= off) ? part[tid - off] : 0;
        __syncthreads();
        part[tid] += v;
        __syncthreads();
    }
    int run = (tid == 0) ? 0 : part[tid - 1];
    for (int j = 0; j < chunk; j++) {
        int idx = base + j;
        if (idx < N) {
            g_rowptr[idx] = run;
            run += g_cnt[idx];
            g_cnt[idx] = 0;   // reset for scatter cursor
        }
    }
    if (tid == 1023) g_rowptr[N] = E;
}

__global__ void scatter_kernel(const int* __restrict__ dst, int E) {
    int i = blockIdx.x * blockDim.x + threadIdx.x;
    if (i < E) {
        int d = dst[i];
        int p = atomicAdd(&g_cnt[d], 1);
        g_elist[g_rowptr[d] + p] = i;
    }
}

// ================= aggregate: warp per node, no atomics =================
template <bool BN>
__global__ void __launch_bounds__(256) agg_kernel(
    const float* __restrict__ z, const float* __restrict__ ea,
    const int* __restrict__ srcI,
    const float* __restrict__ gamma, const float* __restrict__ beta,
    float* __restrict__ agg, int N, float invN) {
    __shared__ float s_sc[HID], s_sh[HID];
    if (BN) {
        if (threadIdx.x < HID) {
            int c = threadIdx.x;
            float mu = g_stat_z[c] * invN;
            float var = g_stat_z[HID + c] * invN - mu * mu;
            float sv = gamma[c] * rsqrtf(var + 1e-5f);
            s_sc[c] = sv;
            s_sh[c] = beta[c] - sv * mu;
        }
        __syncthreads();
    }
    int warp = (blockIdx.x * blockDim.x + threadIdx.x) >> 5;
    int lane = threadIdx.x & 31;
    if (warp >= N) return;

    float4 sc, sh;
    if (BN) {
        sc = *(const float4*)&s_sc[lane * 4];
        sh = *(const float4*)&s_sh[lane * 4];
    }

    int idx = g_rowptr[warp];
    const int end = g_rowptr[warp + 1];
    float4 acc = make_float4(0.f, 0.f, 0.f, 0.f);

    for (; idx + 2 <= end; idx += 2) {
        int e0 = __ldg(g_elist + idx);
        int e1 = __ldg(g_elist + idx + 1);
        int s0 = __ldg(srcI + e0);
        int s1 = __ldg(srcI + e1);
        float4 z0 = __ldg((const float4*)(z + (size_t)s0 * HID) + lane);
        float4 z1 = __ldg((const float4*)(z + (size_t)s1 * HID) + lane);
        float4 a0 = __ldcs((const float4*)(ea + (size_t)e0 * HID) + lane);
        float4 a1 = __ldcs((const float4*)(ea + (size_t)e1 * HID) + lane);
        if (BN) {
            z0.x = fmaf(sc.x, z0.x, sh.x); z0.y = fmaf(sc.y, z0.y, sh.y);
            z0.z = fmaf(sc.z, z0.z, sh.z); z0.w = fmaf(sc.w, z0.w, sh.w);
            z1.x = fmaf(sc.x, z1.x, sh.x); z1.y = fmaf(sc.y, z1.y, sh.y);
            z1.z = fmaf(sc.z, z1.z, sh.z); z1.w = fmaf(sc.w, z1.w, sh.w);
        }
        acc.x += fmaxf(z0.x + a0.x, 0.f) + fmaxf(z1.x + a1.x, 0.f);
        acc.y += fmaxf(z0.y + a0.y, 0.f) + fmaxf(z1.y + a1.y, 0.f);
        acc.z += fmaxf(z0.z + a0.z, 0.f) + fmaxf(z1.z + a1.z, 0.f);
        acc.w += fmaxf(z0.w + a0.w, 0.f) + fmaxf(z1.w + a1.w, 0.f);
    }
    if (idx < end) {
        int e0 = __ldg(g_elist + idx);
        int s0 = __ldg(srcI + e0);
        float4 z0 = __ldg((const float4*)(z + (size_t)s0 * HID) + lane);
        float4 a0 = __ldcs((const float4*)(ea + (size_t)e0 * HID) + lane);
        if (BN) {
            z0.x = fmaf(sc.x, z0.x, sh.x); z0.y = fmaf(sc.y, z0.y, sh.y);
            z0.z = fmaf(sc.z, z0.z, sh.z); z0.w = fmaf(sc.w, z0.w, sh.w);
        }
        acc.x += fmaxf(z0.x + a0.x, 0.f);
        acc.y += fmaxf(z0.y + a0.y, 0.f);
        acc.z += fmaxf(z0.z + a0.z, 0.f);
        acc.w += fmaxf(z0.w + a0.w, 0.f);
    }
    ((float4*)(agg + (size_t)warp * HID))[lane] = acc;  // every row written: no memset
}

// ================= fused GEMM =================
// C[M,128] = post(pre(A) @ W + bias); BM=64, 256 threads, 4x8 thread tile, f32x2 FMA
static const int GEMM_SMEM = (HID * HID + 64 * 132 + 2 * HID) * 4;  // 100352 B

template <bool BN_IN, bool HAS_A2, bool RELU_IN, bool RELU_OUT, bool STATS>
__global__ void __launch_bounds__(256) gemm_kernel(
    const float* __restrict__ A, const float* __restrict__ A2,
    const float* __restrict__ stat_in, const float* __restrict__ gamma,
    const float* __restrict__ beta, float invN,
    const float* __restrict__ W, const float* __restrict__ bias,
    float* __restrict__ out, float* __restrict__ stat_out, int M) {
    extern __shared__ float smem[];
    float* Ws = smem;                        // [128][128]
    float* As = smem + HID * HID;            // [64][132]
    float* s_sc = smem + HID * HID + 64 * 132;
    float* s_sh = s_sc + HID;

    const int tid = threadIdx.x;
    const int tx = tid & 15;
    const int ty = tid >> 4;
    const int row0 = blockIdx.x * 64;

    if (tid < HID) {
        if (BN_IN) {
            float mu = stat_in[tid] * invN;
            float var = stat_in[HID + tid] * invN - mu * mu;
            float sv = gamma[tid] * rsqrtf(var + 1e-5f);
            s_sc[tid] = sv;
            s_sh[tid] = beta[tid] - sv * mu;
        } else {
            s_sc[tid] = 1.f;
            s_sh[tid] = 0.f;
        }
    }

    // stage W (4096 float4)
    const float4* Wg = (const float4*)W;
    float4* Ws4 = (float4*)Ws;
#pragma unroll
    for (int i = 0; i < 16; i++) Ws4[tid + 256 * i] = __ldg(Wg + tid + 256 * i);
    __syncthreads();  // s_sc ready before staging A

    // stage A tile with input transform
    for (int i = tid; i < 64 * 32; i += 256) {
        int r = i >> 5, c4 = i & 31;
        int gr = row0 + r;
        float4 v = make_float4(0.f, 0.f, 0.f, 0.f);
        if (gr < M) {
            float4 zv = __ldg((const float4*)(A + (size_t)gr * HID) + c4);
            float4 s4 = *(const float4*)&s_sc[c4 * 4];
            float4 h4 = *(const float4*)&s_sh[c4 * 4];
            v.x = fmaf(s4.x, zv.x, h4.x);
            v.y = fmaf(s4.y, zv.y, h4.y);
            v.z = fmaf(s4.z, zv.z, h4.z);
            v.w = fmaf(s4.w, zv.w, h4.w);
            if (RELU_IN) {
                v.x = fmaxf(v.x, 0.f); v.y = fmaxf(v.y, 0.f);
                v.z = fmaxf(v.z, 0.f); v.w = fmaxf(v.w, 0.f);
            }
            if (HAS_A2) {
                float4 g4 = __ldg((const float4*)(A2 + (size_t)gr * HID) + c4);
                v.x += g4.x; v.y += g4.y; v.z += g4.z; v.w += g4.w;
            }
        }
        *(float4*)&As[r * 132 + c4 * 4] = v;
    }
    __syncthreads();

    unsigned long long acc[16];
#pragma unroll
    for (int i = 0; i < 16; i++) acc[i] = 0ull;

    const int arow = ty * 4;
#pragma unroll 2
    for (int kk = 0; kk < HID; kk += 4) {
        float ar[4][4];
#pragma unroll
        for (int r = 0; r < 4; r++)
            *(float4*)ar[r] = *(const float4*)&As[(arow + r) * 132 + kk];
#pragma unroll
        for (int j = 0; j < 4; j++) {
            ulonglong2 wA = *(const ulonglong2*)&Ws[(kk + j) * HID + tx * 8];
            ulonglong2 wB = *(const ulonglong2*)&Ws[(kk + j) * HID + tx * 8 + 4];
#pragma unroll
            for (int r = 0; r < 4; r++) {
                unsigned long long pa = pk2(ar[r][j]);
                fma2(acc[r * 4 + 0], pa, wA.x);
                fma2(acc[r * 4 + 1], pa, wA.y);
                fma2(acc[r * 4 + 2], pa, wB.x);
                fma2(acc[r * 4 + 3], pa, wB.y);
            }
        }
    }

    // epilogue
    float bb[8];
    *(float4*)&bb[0] = __ldg((const float4*)bias + tx * 2);
    *(float4*)&bb[4] = __ldg((const float4*)bias + tx * 2 + 1);
    float csum[8], csq[8];
#pragma unroll
    for (int j = 0; j < 8; j++) { csum[j] = 0.f; csq[j] = 0.f; }

#pragma unroll
    for (int r = 0; r < 4; r++) {
        int gr = row0 + arow + r;
        if (gr < M) {
            float v[8];
#pragma unroll
            for (int p = 0; p < 4; p++) {
                float2 u = upk(acc[r * 4 + p]);
                v[2 * p] = u.x + bb[2 * p];
                v[2 * p + 1] = u.y + bb[2 * p + 1];
            }
            if (RELU_OUT) {
#pragma unroll
                for (int j = 0; j < 8; j++) v[j] = fmaxf(v[j], 0.f);
            }
            *(float4*)(out + (size_t)gr * HID + tx * 8) = make_float4(v[0], v[1], v[2], v[3]);
            *(float4*)(out + (size_t)gr * HID + tx * 8 + 4) = make_float4(v[4], v[5], v[6], v[7]);
            if (STATS) {
#pragma unroll
                for (int j = 0; j < 8; j++) { csum[j] += v[j]; csq[j] += v[j] * v[j]; }
            }
        }
    }

    if (STATS) {
        float* red = As;  // reuse
        __syncthreads();
#pragma unroll
        for (int j = 0; j < 8; j++) red[ty * HID + tx * 8 + j] = csum[j];
        __syncthreads();
        for (int s = 8; s > 0; s >>= 1) {
            if (ty < s) {
#pragma unroll
                for (int j = 0; j < 8; j++)
                    red[ty * HID + tx * 8 + j] += red[(ty + s) * HID + tx * 8 + j];
            }
            __syncthreads();
        }
        if (ty == 0) {
#pragma unroll
            for (int j = 0; j < 8; j++) atomicAdd(&stat_out[tx * 8 + j], red[tx * 8 + j]);
        }
        __syncthreads();
#pragma unroll
        for (int j = 0; j < 8; j++) red[ty * HID + tx * 8 + j] = csq[j];
        __syncthreads();
        for (int s = 8; s > 0; s >>= 1) {
            if (ty < s) {
#pragma unroll
                for (int j = 0; j < 8; j++)
                    red[ty * HID + tx * 8 + j] += red[(ty + s) * HID + tx * 8 + j];
            }
            __syncthreads();
        }
        if (ty == 0) {
#pragma unroll
            for (int j = 0; j < 8; j++) atomicAdd(&stat_out[HID + tx * 8 + j], red[tx * 8 + j]);
        }
    }
}

// ================= launcher =================
extern "C" void kernel_launch(void* const* d_in, const int* in_sizes, int n_in,
                              void* d_out, int out_size) {
    const float* x = (const float*)d_in[0];
    const int* ei = (const int*)d_in[1];   // int32 (JAX default, x64 disabled)
    const float* ea = (const float*)d_in[2];
    const float* W1 = (const float*)d_in[3];
    const float* b1 = (const float*)d_in[4];
    const float* g1 = (const float*)d_in[5];
    const float* be1 = (const float*)d_in[6];
    const float* W2 = (const float*)d_in[7];
    const float* b2 = (const float*)d_in[8];
    const float* bn_g = (const float*)d_in[9];
    const float* bn_b = (const float*)d_in[10];

    int M = in_sizes[0] / HID;
    int E = in_sizes[2] / HID;
    float* out = (float*)d_out;

    void *agg_p, *z_p, *t_p, *cnt_p, *stat_t_p, *stat_z_p;
    cudaGetSymbolAddress(&agg_p, g_agg);
    cudaGetSymbolAddress(&z_p, g_z);
    cudaGetSymbolAddress(&t_p, g_t);
    cudaGetSymbolAddress(&cnt_p, g_cnt);
    cudaGetSymbolAddress(&stat_t_p, g_stat_t);
    cudaGetSymbolAddress(&stat_z_p, g_stat_z);

    cudaFuncSetAttribute(gemm_kernel<false, true, false, false, true>,
                         cudaFuncAttributeMaxDynamicSharedMemorySize, GEMM_SMEM);
    cudaFuncSetAttribute(gemm_kernel<true, true, false, false, true>,
                         cudaFuncAttributeMaxDynamicSharedMemorySize, GEMM_SMEM);
    cudaFuncSetAttribute(gemm_kernel<true, false, true, true, true>,
                         cudaFuncAttributeMaxDynamicSharedMemorySize, GEMM_SMEM);
    cudaFuncSetAttribute(gemm_kernel<true, false, true, true, false>,
                         cudaFuncAttributeMaxDynamicSharedMemorySize, GEMM_SMEM);

    const int* srcI = ei;
    const int* dstI = ei + E;
    int eb = (E + 255) / 256;
    int gb = (M + 63) / 64;
    int ab = (M * 32 + 255) / 256;   // warp per node
    float invN = 1.0f / (float)M;

    // ---- CSR build (once per call) ----
    cudaMemsetAsync(cnt_p, 0, (size_t)M * sizeof(int));
    hist_kernel<<<eb, 256>>>(dstI, E);
    scan_kernel<<<1, 1024>>>(M, E);
    scatter_kernel<<<eb, 256>>>(dstI, E);

    for (int i = 0; i < 4; i++) {
        const float* zsrc = (i == 0) ? x : (const float*)z_p;

        if (i == 0)
            agg_kernel<false><<<ab, 256>>>(zsrc, ea, srcI, nullptr, nullptr,
                                           (float*)agg_p, M, invN);
        else
            agg_kernel<true><<<ab, 256>>>(zsrc, ea, srcI,
                                          bn_g + (size_t)(i - 1) * HID,
                                          bn_b + (size_t)(i - 1) * HID,
                                          (float*)agg_p, M, invN);

        cudaMemsetAsync(stat_t_p, 0, 2 * HID * sizeof(float));

        if (i == 0)
            gemm_kernel<false, true, false, false, true><<<gb, 256, GEMM_SMEM>>>(
                zsrc, (const float*)agg_p, nullptr, nullptr, nullptr, invN,
                W1, b1, (float*)t_p, (float*)stat_t_p, M);
        else
            gemm_kernel<true, true, false, false, true><<<gb, 256, GEMM_SMEM>>>(
                zsrc, (const float*)agg_p, (const float*)stat_z_p,
                bn_g + (size_t)(i - 1) * HID, bn_b + (size_t)(i - 1) * HID, invN,
                W1 + (size_t)i * HID * HID, b1 + (size_t)i * HID,
                (float*)t_p, (float*)stat_t_p, M);

        if (i < 3) {
            cudaMemsetAsync(stat_z_p, 0, 2 * HID * sizeof(float));
            gemm_kernel<true, false, true, true, true><<<gb, 256, GEMM_SMEM>>>(
                (const float*)t_p, nullptr, (const float*)stat_t_p,
                g1 + (size_t)i * HID, be1 + (size_t)i * HID, invN,
                W2 + (size_t)i * HID * HID, b2 + (size_t)i * HID,
                (float*)z_p, (float*)stat_z_p, M);
        } else {
            gemm_kernel<true, false, true, true, false><<<gb, 256, GEMM_SMEM>>>(
                (const float*)t_p, nullptr, (const float*)stat_t_p,
                g1 + (size_t)i * HID, be1 + (size_t)i * HID, invN,
                W2 + (size_t)i * HID * HID, b2 + (size_t)i * HID,
                out, nullptr, M);
        }
    }
}

// round 4
// speedup vs baseline: 1.6488x; 1.5730x over previous
#include <cuda_runtime.h>
#include <cstdint>

#define HID 128
#define MAXN 50000
#define MAXE 640000

// ---------------- scratch (device globals; no allocation allowed) ----------------
__device__ __align__(256) float g_z[MAXN * HID];     // raw (pre-BN) layer output
__device__ __align__(256) float g_agg[MAXN * HID];   // edge aggregation
__device__ __align__(256) float g_t[MAXN * HID];     // post-GEMM1 pre-BN
__device__ __align__(256) float g_stat_t[2 * HID];   // stats of t (after GEMM1)
__device__ __align__(256) float g_stat_z[2 * HID];   // stats of z (after GEMM2)
__device__ int g_cnt[MAXN];                          // histogram / scatter cursor
__device__ int g_rowptr[MAXN + 1];
__device__ int g_elist[MAXE];

// ---------------- f32x2 helpers (sm_100+ packed fp32 pipe) ----------------
__device__ __forceinline__ unsigned long long pk2(float a) {
    unsigned long long r;
    asm("mov.b64 %0, {%1, %1};" : "=l"(r) : "f"(a));
    return r;
}
__device__ __forceinline__ void fma2(unsigned long long& d, unsigned long long a, unsigned long long b) {
    asm("fma.rn.f32x2 %0, %1, %2, %0;" : "+l"(d) : "l"(a), "l"(b));
}
__device__ __forceinline__ float2 upk(unsigned long long v) {
    float2 r;
    asm("mov.b64 {%0, %1}, %2;" : "=f"(r.x), "=f"(r.y) : "l"(v));
    return r;
}

// ================= CSR build =================
__global__ void hist_kernel(const int* __restrict__ dst, int E) {
    int i = blockIdx.x * blockDim.x + threadIdx.x;
    if (i < E) atomicAdd(&g_cnt[dst[i]], 1);
}

__global__ void __launch_bounds__(1024) scan_kernel(int N, int E) {
    __shared__ int part[1024];
    int tid = threadIdx.x;
    int chunk = (N + 1023) / 1024;
    int base = tid * chunk;
    int s = 0;
    for (int j = 0; j < chunk; j++) {
        int idx = base + j;
        if (idx < N) s += g_cnt[idx];
    }
    part[tid] = s;
    __syncthreads();
    for (int off = 1; off < 1024; off <<= 1) {
        int v = (tid >= off) ? part[tid - off] : 0;
        __syncthreads();
        part[tid] += v;
        __syncthreads();
    }
    int run = (tid == 0) ? 0 : part[tid - 1];
    for (int j = 0; j < chunk; j++) {
        int idx = base + j;
        if (idx < N) {
            g_rowptr[idx] = run;
            run += g_cnt[idx];
            g_cnt[idx] = 0;   // reset for scatter cursor
        }
    }
    if (tid == 1023) g_rowptr[N] = E;
}

__global__ void scatter_kernel(const int* __restrict__ dst, int E) {
    int i = blockIdx.x * blockDim.x + threadIdx.x;
    if (i < E) {
        int d = dst[i];
        int p = atomicAdd(&g_cnt[d], 1);
        g_elist[g_rowptr[d] + p] = i;
    }
}

// ================= aggregate: warp per node, no atomics =================
template <bool BN>
__global__ void __launch_bounds__(256) agg_kernel(
    const float* __restrict__ z, const float* __restrict__ ea,
    const int* __restrict__ srcI,
    const float* __restrict__ gamma, const float* __restrict__ beta,
    float* __restrict__ agg, int N, float invN) {
    __shared__ float s_sc[HID], s_sh[HID];
    if (BN) {
        if (threadIdx.x < HID) {
            int c = threadIdx.x;
            float mu = g_stat_z[c] * invN;
            float var = g_stat_z[HID + c] * invN - mu * mu;
            float sv = gamma[c] * rsqrtf(var + 1e-5f);
            s_sc[c] = sv;
            s_sh[c] = beta[c] - sv * mu;
        }
        __syncthreads();
    }
    int warp = (blockIdx.x * blockDim.x + threadIdx.x) >> 5;
    int lane = threadIdx.x & 31;
    if (warp >= N) return;

    float4 sc, sh;
    if (BN) {
        sc = *(const float4*)&s_sc[lane * 4];
        sh = *(const float4*)&s_sh[lane * 4];
    }

    int idx = g_rowptr[warp];
    const int end = g_rowptr[warp + 1];
    float4 acc = make_float4(0.f, 0.f, 0.f, 0.f);

#define EDGE_BODY(E_, S_)                                                     \
    {                                                                         \
        float4 zv = __ldg((const float4*)(z + (size_t)(S_) * HID) + lane);    \
        float4 av = __ldcs((const float4*)(ea + (size_t)(E_) * HID) + lane);  \
        if (BN) {                                                             \
            zv.x = fmaf(sc.x, zv.x, sh.x); zv.y = fmaf(sc.y, zv.y, sh.y);     \
            zv.z = fmaf(sc.z, zv.z, sh.z); zv.w = fmaf(sc.w, zv.w, sh.w);     \
        }                                                                     \
        acc.x += fmaxf(zv.x + av.x, 0.f);                                     \
        acc.y += fmaxf(zv.y + av.y, 0.f);                                     \
        acc.z += fmaxf(zv.z + av.z, 0.f);                                     \
        acc.w += fmaxf(zv.w + av.w, 0.f);                                     \
    }

    for (; idx + 4 <= end; idx += 4) {
        int e0 = __ldg(g_elist + idx);
        int e1 = __ldg(g_elist + idx + 1);
        int e2 = __ldg(g_elist + idx + 2);
        int e3 = __ldg(g_elist + idx + 3);
        int s0 = __ldg(srcI + e0);
        int s1 = __ldg(srcI + e1);
        int s2 = __ldg(srcI + e2);
        int s3 = __ldg(srcI + e3);
        EDGE_BODY(e0, s0) EDGE_BODY(e1, s1) EDGE_BODY(e2, s2) EDGE_BODY(e3, s3)
    }
    for (; idx < end; idx++) {
        int e0 = __ldg(g_elist + idx);
        int s0 = __ldg(srcI + e0);
        EDGE_BODY(e0, s0)
    }
#undef EDGE_BODY
    ((float4*)(agg + (size_t)warp * HID))[lane] = acc;  // every row written: no memset
}

// ================= fused GEMM =================
// C[M,128] = post(pre(A) @ W + bias); BM=64, 256 threads.
// Warp w owns rows w*8..w*8+7; lane owns cols lane*4..lane*4+3 (conflict-free W LDS).
static const int GEMM_SMEM = (HID * HID + 64 * 132 + 2 * HID) * 4;  // 100352 B

template <bool BN_IN, bool HAS_A2, bool RELU_IN, bool RELU_OUT, bool STATS>
__global__ void __launch_bounds__(256) gemm_kernel(
    const float* __restrict__ A, const float* __restrict__ A2,
    const float* __restrict__ stat_in, const float* __restrict__ gamma,
    const float* __restrict__ beta, float invN,
    const float* __restrict__ W, const float* __restrict__ bias,
    float* __restrict__ out, float* __restrict__ stat_out, int M) {
    extern __shared__ float smem[];
    float* Ws = smem;                        // [128][128]
    float* As = smem + HID * HID;            // [64][132]
    float* s_sc = smem + HID * HID + 64 * 132;
    float* s_sh = s_sc + HID;

    const int tid = threadIdx.x;
    const int lane = tid & 31;
    const int wid = tid >> 5;
    const int row0 = blockIdx.x * 64;

    if (tid < HID) {
        if (BN_IN) {
            float mu = stat_in[tid] * invN;
            float var = stat_in[HID + tid] * invN - mu * mu;
            float sv = gamma[tid] * rsqrtf(var + 1e-5f);
            s_sc[tid] = sv;
            s_sh[tid] = beta[tid] - sv * mu;
        } else {
            s_sc[tid] = 1.f;
            s_sh[tid] = 0.f;
        }
    }

    // stage W (4096 float4)
    const float4* Wg = (const float4*)W;
    float4* Ws4 = (float4*)Ws;
#pragma unroll
    for (int i = 0; i < 16; i++) Ws4[tid + 256 * i] = __ldg(Wg + tid + 256 * i);
    __syncthreads();  // s_sc ready before staging A

    // stage A tile with input transform
    for (int i = tid; i < 64 * 32; i += 256) {
        int r = i >> 5, c4 = i & 31;
        int gr = row0 + r;
        float4 v = make_float4(0.f, 0.f, 0.f, 0.f);
        if (gr < M) {
            float4 zv = __ldg((const float4*)(A + (size_t)gr * HID) + c4);
            float4 s4 = *(const float4*)&s_sc[c4 * 4];
            float4 h4 = *(const float4*)&s_sh[c4 * 4];
            v.x = fmaf(s4.x, zv.x, h4.x);
            v.y = fmaf(s4.y, zv.y, h4.y);
            v.z = fmaf(s4.z, zv.z, h4.z);
            v.w = fmaf(s4.w, zv.w, h4.w);
            if (RELU_IN) {
                v.x = fmaxf(v.x, 0.f); v.y = fmaxf(v.y, 0.f);
                v.z = fmaxf(v.z, 0.f); v.w = fmaxf(v.w, 0.f);
            }
            if (HAS_A2) {
                float4 g4 = __ldg((const float4*)(A2 + (size_t)gr * HID) + c4);
                v.x += g4.x; v.y += g4.y; v.z += g4.z; v.w += g4.w;
            }
        }
        *(float4*)&As[r * 132 + c4 * 4] = v;
    }
    __syncthreads();

    // acc[r][0..1]: row r (of 8), packed col pairs {lane*4,lane*4+1},{lane*4+2,lane*4+3}
    unsigned long long acc[16];
#pragma unroll
    for (int i = 0; i < 16; i++) acc[i] = 0ull;

    const int arow = wid * 8;
#pragma unroll 2
    for (int kk = 0; kk < HID; kk += 4) {
        float ar[8][4];
#pragma unroll
        for (int r = 0; r < 8; r++)
            *(float4*)ar[r] = *(const float4*)&As[(arow + r) * 132 + kk];  // warp-uniform bcast
#pragma unroll
        for (int j = 0; j < 4; j++) {
            // conflict-free: lane*16B, 512B row, 4 phases x 32 banks
            ulonglong2 w = *(const ulonglong2*)&Ws[(kk + j) * HID + lane * 4];
#pragma unroll
            for (int r = 0; r < 8; r++) {
                unsigned long long pa = pk2(ar[r][j]);
                fma2(acc[r * 2 + 0], pa, w.x);
                fma2(acc[r * 2 + 1], pa, w.y);
            }
        }
    }

    // epilogue: lane's 4 contiguous cols
    float bb[4];
    *(float4*)bb = __ldg((const float4*)bias + lane);
    float csum[4], csq[4];
#pragma unroll
    for (int j = 0; j < 4; j++) { csum[j] = 0.f; csq[j] = 0.f; }

#pragma unroll
    for (int r = 0; r < 8; r++) {
        int gr = row0 + arow + r;
        if (gr < M) {
            float2 u0 = upk(acc[r * 2 + 0]);
            float2 u1 = upk(acc[r * 2 + 1]);
            float v[4] = {u0.x + bb[0], u0.y + bb[1], u1.x + bb[2], u1.y + bb[3]};
            if (RELU_OUT) {
#pragma unroll
                for (int j = 0; j < 4; j++) v[j] = fmaxf(v[j], 0.f);
            }
            *(float4*)(out + (size_t)gr * HID + lane * 4) = make_float4(v[0], v[1], v[2], v[3]);
            if (STATS) {
#pragma unroll
                for (int j = 0; j < 4; j++) { csum[j] += v[j]; csq[j] += v[j] * v[j]; }
            }
        }
    }

    if (STATS) {
        // red[wid][0..127]=sum, red[wid][128..255]=sumsq ; 8x256 floats, reuse As
        float* red = As;
        __syncthreads();
#pragma unroll
        for (int j = 0; j < 4; j++) {
            red[wid * 256 + lane * 4 + j] = csum[j];
            red[wid * 256 + 128 + lane * 4 + j] = csq[j];
        }
        __syncthreads();
#pragma unroll
        for (int s = 4; s > 0; s >>= 1) {
            if (wid < s) {
                for (int i = lane; i < 256; i += 32)
                    red[wid * 256 + i] += red[(wid + s) * 256 + i];
            }
            __syncthreads();
        }
        if (wid == 0) {
#pragma unroll
            for (int j = 0; j < 4; j++) {
                atomicAdd(&stat_out[lane * 4 + j], red[lane * 4 + j]);
                atomicAdd(&stat_out[HID + lane * 4 + j], red[128 + lane * 4 + j]);
            }
        }
    }
}

// ================= launcher =================
extern "C" void kernel_launch(void* const* d_in, const int* in_sizes, int n_in,
                              void* d_out, int out_size) {
    const float* x = (const float*)d_in[0];
    const int* ei = (const int*)d_in[1];   // int32 (JAX default, x64 disabled)
    const float* ea = (const float*)d_in[2];
    const float* W1 = (const float*)d_in[3];
    const float* b1 = (const float*)d_in[4];
    const float* g1 = (const float*)d_in[5];
    const float* be1 = (const float*)d_in[6];
    const float* W2 = (const float*)d_in[7];
    const float* b2 = (const float*)d_in[8];
    const float* bn_g = (const float*)d_in[9];
    const float* bn_b = (const float*)d_in[10];

    int M = in_sizes[0] / HID;
    int E = in_sizes[2] / HID;
    float* out = (float*)d_out;

    void *agg_p, *z_p, *t_p, *cnt_p, *stat_t_p, *stat_z_p;
    cudaGetSymbolAddress(&agg_p, g_agg);
    cudaGetSymbolAddress(&z_p, g_z);
    cudaGetSymbolAddress(&t_p, g_t);
    cudaGetSymbolAddress(&cnt_p, g_cnt);
    cudaGetSymbolAddress(&stat_t_p, g_stat_t);
    cudaGetSymbolAddress(&stat_z_p, g_stat_z);

    cudaFuncSetAttribute(gemm_kernel<false, true, false, false, true>,
                         cudaFuncAttributeMaxDynamicSharedMemorySize, GEMM_SMEM);
    cudaFuncSetAttribute(gemm_kernel<true, true, false, false, true>,
                         cudaFuncAttributeMaxDynamicSharedMemorySize, GEMM_SMEM);
    cudaFuncSetAttribute(gemm_kernel<true, false, true, true, true>,
                         cudaFuncAttributeMaxDynamicSharedMemorySize, GEMM_SMEM);
    cudaFuncSetAttribute(gemm_kernel<true, false, true, true, false>,
                         cudaFuncAttributeMaxDynamicSharedMemorySize, GEMM_SMEM);

    const int* srcI = ei;
    const int* dstI = ei + E;
    int eb = (E + 255) / 256;
    int gb = (M + 63) / 64;
    int ab = (M * 32 + 255) / 256;   // warp per node
    float invN = 1.0f / (float)M;

    // ---- CSR build (once per call) ----
    cudaMemsetAsync(cnt_p, 0, (size_t)M * sizeof(int));
    hist_kernel<<<eb, 256>>>(dstI, E);
    scan_kernel<<<1, 1024>>>(M, E);
    scatter_kernel<<<eb, 256>>>(dstI, E);

    for (int i = 0; i < 4; i++) {
        const float* zsrc = (i == 0) ? x : (const float*)z_p;

        if (i == 0)
            agg_kernel<false><<<ab, 256>>>(zsrc, ea, srcI, nullptr, nullptr,
                                           (float*)agg_p, M, invN);
        else
            agg_kernel<true><<<ab, 256>>>(zsrc, ea, srcI,
                                          bn_g + (size_t)(i - 1) * HID,
                                          bn_b + (size_t)(i - 1) * HID,
                                          (float*)agg_p, M, invN);

        cudaMemsetAsync(stat_t_p, 0, 2 * HID * sizeof(float));

        if (i == 0)
            gemm_kernel<false, true, false, false, true><<<gb, 256, GEMM_SMEM>>>(
                zsrc, (const float*)agg_p, nullptr, nullptr, nullptr, invN,
                W1, b1, (float*)t_p, (float*)stat_t_p, M);
        else
            gemm_kernel<true, true, false, false, true><<<gb, 256, GEMM_SMEM>>>(
                zsrc, (const float*)agg_p, (const float*)stat_z_p,
                bn_g + (size_t)(i - 1) * HID, bn_b + (size_t)(i - 1) * HID, invN,
                W1 + (size_t)i * HID * HID, b1 + (size_t)i * HID,
                (float*)t_p, (float*)stat_t_p, M);

        if (i < 3) {
            cudaMemsetAsync(stat_z_p, 0, 2 * HID * sizeof(float));
            gemm_kernel<true, false, true, true, true><<<gb, 256, GEMM_SMEM>>>(
                (const float*)t_p, nullptr, (const float*)stat_t_p,
                g1 + (size_t)i * HID, be1 + (size_t)i * HID, invN,
                W2 + (size_t)i * HID * HID, b2 + (size_t)i * HID,
                (float*)z_p, (float*)stat_z_p, M);
        } else {
            gemm_kernel<true, false, true, true, false><<<gb, 256, GEMM_SMEM>>>(
                (const float*)t_p, nullptr, (const float*)stat_t_p,
                g1 + (size_t)i * HID, be1 + (size_t)i * HID, invN,
                W2 + (size_t)i * HID * HID, b2 + (size_t)i * HID,
                out, nullptr, M);
        }
    }
}